// round 5
// baseline (speedup 1.0000x reference)
#include <cuda_runtime.h>
#include <math.h>

#define NN 100000
#define EE 1600000
#define D  128
#define BN_EPS 1e-5f

// ---------------- scratch (device globals; allocation-free kernel_launch) ----
__device__ float g_h [NN * D];
__device__ float g_y [NN * D];
__device__ float g_xa[NN * D];
__device__ float g_xb[NN * D];

__device__ int   g_deg[NN];
__device__ float g_dinv[NN];
__device__ int   g_incl[NN];
__device__ int   g_start[NN];
__device__ int   g_cursor[NN];
__device__ int   g_bsum[256];
__device__ int   g_boff[256];

__device__ int   g_csr_src[EE];
__device__ float g_csr_w [EE];

__device__ float g_sum[D], g_sq[D], g_scale[D], g_shift[D];

__device__ int   g_is64;

// ---------------- edge-index dtype detection --------------------------------
// If the buffer holds int64 values < 100000, every odd 32-bit word is 0.
// If it holds int32 indices, odd words are random in [0, 100000) — the chance
// all 16 samples are zero is ~1e-80.
__global__ void k_detect(const int* __restrict__ ei) {
    if (threadIdx.x == 0 && blockIdx.x == 0) {
        int is64 = 1;
        #pragma unroll
        for (int i = 0; i < 16; i++)
            if (ei[2 * i + 1] != 0) is64 = 0;
        g_is64 = is64;
    }
}

__device__ __forceinline__ int load_idx(const void* ei, long long pos) {
    if (g_is64) return (int)((const long long*)ei)[pos];
    return ((const int*)ei)[pos];
}

// ---------------- pre-pass: degrees, dinv, CSR ------------------------------
__global__ void k_zero_deg(int n) {
    int i = blockIdx.x * blockDim.x + threadIdx.x;
    if (i < n) g_deg[i] = 0;
}

__global__ void k_deg(const void* __restrict__ ei, int e, int n) {
    int i = blockIdx.x * blockDim.x + threadIdx.x;
    if (i < e) {
        int dst = load_idx(ei, (long long)e + i);
        if ((unsigned)dst < (unsigned)n)
            atomicAdd(&g_deg[dst], 1);
    }
}

__global__ void k_dinv(int n) {
    int i = blockIdx.x * blockDim.x + threadIdx.x;
    if (i < n) g_dinv[i] = rsqrtf((float)(g_deg[i] + 1));   // +1 self loop
}

// inclusive scan per 1024-block
__global__ void k_scan_a(int n) {
    __shared__ int s[1024];
    int t = threadIdx.x;
    int i = blockIdx.x * 1024 + t;
    int v = (i < n) ? g_deg[i] : 0;
    s[t] = v;
    __syncthreads();
    for (int off = 1; off < 1024; off <<= 1) {
        int u = (t >= off) ? s[t - off] : 0;
        __syncthreads();
        s[t] += u;
        __syncthreads();
    }
    if (i < n) g_incl[i] = s[t];
    if (t == 1023) g_bsum[blockIdx.x] = s[1023];
}

__global__ void k_scan_b(int nb) {
    if (threadIdx.x == 0) {
        int acc = 0;
        for (int b = 0; b < nb; b++) { g_boff[b] = acc; acc += g_bsum[b]; }
    }
}

__global__ void k_scan_c(int n) {
    int i = blockIdx.x * blockDim.x + threadIdx.x;
    if (i < n) {
        int st = g_incl[i] + g_boff[i >> 10] - g_deg[i];  // exclusive start
        g_start[i]  = st;
        g_cursor[i] = st;
    }
}

__global__ void k_fill(const void* __restrict__ ei, int e, int n) {
    int i = blockIdx.x * blockDim.x + threadIdx.x;
    if (i < e) {
        int s = load_idx(ei, i);
        int d = load_idx(ei, (long long)e + i);
        if ((unsigned)s < (unsigned)n && (unsigned)d < (unsigned)n) {
            int p = atomicAdd(&g_cursor[d], 1);
            if ((unsigned)p < (unsigned)EE) {
                g_csr_src[p] = s;
                g_csr_w[p]   = g_dinv[s] * g_dinv[d];
            }
        }
    }
}

// ---------------- GEMM: h = x @ W (W row-major [K][C]) ----------------------
// 256 threads (8 warps), each warp computes 8 rows; W resident in smem.
#define GEMM_WARPS  8
#define ROWS_PER_W  8
#define GEMM_SMEM   ((D * D + GEMM_WARPS * ROWS_PER_W * D) * (int)sizeof(float))

__device__ __forceinline__ const float* sel_x(int s, const float* ext) {
    return (s == 0) ? ext : ((s == 1) ? g_xa : g_xb);
}

__global__ __launch_bounds__(256)
void k_gemm(int xsel, const float* __restrict__ xext,
            const float* __restrict__ W, int n) {
    extern __shared__ float sm[];
    float* Ws = sm;                       // D*D
    float* Xs = sm + D * D;               // 8 warps * 8 rows * D
    const float* x = sel_x(xsel, xext);

    for (int i = threadIdx.x; i < D * D / 4; i += blockDim.x)
        ((float4*)Ws)[i] = ((const float4*)W)[i];
    __syncthreads();

    int warp = threadIdx.x >> 5;
    int lane = threadIdx.x & 31;
    float* xs = Xs + warp * ROWS_PER_W * D;
    const float4* Ws4 = (const float4*)Ws;

    int taskStride = gridDim.x * GEMM_WARPS;
    int nTasks = (n + ROWS_PER_W - 1) / ROWS_PER_W;
    for (int task = blockIdx.x * GEMM_WARPS + warp; task < nTasks; task += taskStride) {
        int row0 = task * ROWS_PER_W;
        // stage rows
        #pragma unroll
        for (int r = 0; r < ROWS_PER_W; r++) {
            int rr = row0 + r;
            if (rr < n)
                ((float4*)(xs + r * D))[lane] =
                    ((const float4*)(x + (size_t)rr * D))[lane];
        }
        __syncwarp();

        float4 acc[ROWS_PER_W];
        #pragma unroll
        for (int r = 0; r < ROWS_PER_W; r++) acc[r] = make_float4(0.f, 0.f, 0.f, 0.f);

        #pragma unroll 4
        for (int k = 0; k < D; k++) {
            float4 w = Ws4[k * 32 + lane];
            #pragma unroll
            for (int r = 0; r < ROWS_PER_W; r++) {
                float xv = xs[r * D + k];
                acc[r].x += xv * w.x;
                acc[r].y += xv * w.y;
                acc[r].z += xv * w.z;
                acc[r].w += xv * w.w;
            }
        }

        #pragma unroll
        for (int r = 0; r < ROWS_PER_W; r++) {
            int rr = row0 + r;
            if (rr < n)
                ((float4*)(g_h + (size_t)rr * D))[lane] = acc[r];
        }
        __syncwarp();
    }
}

// ---------------- aggregation: y[i] = b + dinv[i]^2*h[i] + sum w*h[src] -----
__global__ void k_gather(const float* __restrict__ bias, int ysel,
                         float* __restrict__ yext, int n) {
    int gw   = (blockIdx.x * blockDim.x + threadIdx.x) >> 5;
    int lane = threadIdx.x & 31;
    if (gw >= n) return;
    int i = gw;
    float* y = (ysel == 0) ? g_y : yext;

    float dv = g_dinv[i];
    float4 acc = ((const float4*)bias)[lane];
    float4 hv  = ((const float4*)(g_h + (size_t)i * D))[lane];
    float c = dv * dv;
    acc.x += c * hv.x; acc.y += c * hv.y; acc.z += c * hv.z; acc.w += c * hv.w;

    int j = g_start[i];
    int e = j + g_deg[i];
    if (e > EE) e = EE;
    if (j < e) {
        int   src = g_csr_src[j];
        float w   = g_csr_w[j];
        while (j < e) {
            int nj = j + 1;
            int nsrc = 0; float nw = 0.f;
            if (nj < e) { nsrc = g_csr_src[nj]; nw = g_csr_w[nj]; }  // prefetch
            float4 hs = ((const float4*)(g_h + (size_t)src * D))[lane];
            acc.x += w * hs.x; acc.y += w * hs.y;
            acc.z += w * hs.z; acc.w += w * hs.w;
            src = nsrc; w = nw; j = nj;
        }
    }
    ((float4*)(y + (size_t)i * D))[lane] = acc;
}

// ---------------- BatchNorm ---------------------------------------------------
__global__ void k_bnzero() {
    int c = threadIdx.x;
    g_sum[c] = 0.f; g_sq[c] = 0.f;
}

__global__ void k_stats(int n) {
    int c = threadIdx.x;        // 128 threads = channels
    float s = 0.f, q = 0.f;
    for (int r = blockIdx.x; r < n; r += gridDim.x) {
        float v = g_y[(size_t)r * D + c];
        s += v; q += v * v;
    }
    atomicAdd(&g_sum[c], s);
    atomicAdd(&g_sq[c],  q);
}

__global__ void k_bnfin(const float* __restrict__ gamma,
                        const float* __restrict__ beta, float inv_n) {
    int c = threadIdx.x;
    float mu  = g_sum[c] * inv_n;
    float var = g_sq[c] * inv_n - mu * mu;
    float sc  = gamma[c] * rsqrtf(var + BN_EPS);
    g_scale[c] = sc;
    g_shift[c] = beta[c] - mu * sc;
}

// normalize + relu + optional residual; float4 over the full tensor
__global__ void k_norm(int resSel, int outSel, int total4) {
    int i = blockIdx.x * blockDim.x + threadIdx.x;
    if (i >= total4) return;
    int c4 = i & (D / 4 - 1);
    float4 v  = ((const float4*)g_y)[i];
    float4 sc = ((const float4*)g_scale)[c4];
    float4 sh = ((const float4*)g_shift)[c4];
    v.x = fmaxf(v.x * sc.x + sh.x, 0.f);
    v.y = fmaxf(v.y * sc.y + sh.y, 0.f);
    v.z = fmaxf(v.z * sc.z + sh.z, 0.f);
    v.w = fmaxf(v.w * sc.w + sh.w, 0.f);
    if (resSel) {
        const float4* res = (resSel == 1) ? (const float4*)g_xa : (const float4*)g_xb;
        float4 rv = res[i];
        v.x += rv.x; v.y += rv.y; v.z += rv.z; v.w += rv.w;
    }
    float4* out = (outSel == 1) ? (float4*)g_xa : (float4*)g_xb;
    out[i] = v;
}

// ---------------- launch ------------------------------------------------------
extern "C" void kernel_launch(void* const* d_in, const int* in_sizes, int n_in,
                              void* d_out, int out_size) {
    const float* x     = (const float*)d_in[0];
    const void*  ei    = d_in[1];                 // int32 OR int64, detected on device
    const float* W0    = (const float*)d_in[2];
    const float* b0    = (const float*)d_in[3];
    const float* Wmid  = (const float*)d_in[4];
    const float* bmid  = (const float*)d_in[5];
    const float* Wlast = (const float*)d_in[6];
    const float* blast = (const float*)d_in[7];
    const float* gamma = (const float*)d_in[8];
    const float* beta  = (const float*)d_in[9];

    int n = in_sizes[0] / D;     // 100000
    int e = in_sizes[1] / 2;     // 1600000

    cudaFuncSetAttribute(k_gemm, cudaFuncAttributeMaxDynamicSharedMemorySize, GEMM_SMEM);

    // ---- pre: dtype detect, degrees / dinv / CSR-by-dst ----
    k_detect<<<1, 32>>>((const int*)ei);
    k_zero_deg<<<(n + 255) / 256, 256>>>(n);
    k_deg<<<(e + 255) / 256, 256>>>(ei, e, n);
    k_dinv<<<(n + 255) / 256, 256>>>(n);
    int nb = (n + 1023) / 1024;
    k_scan_a<<<nb, 1024>>>(n);
    k_scan_b<<<1, 32>>>(nb);
    k_scan_c<<<(n + 255) / 256, 256>>>(n);
    k_fill<<<(e + 255) / 256, 256>>>(ei, e, n);

    int gemmGrid   = 296;                       // ~2 blocks/SM, grid-stride
    int gatherGrid = (n * 32 + 255) / 256;      // warp per node
    int total4     = n * (D / 4);
    int normGrid   = (total4 + 255) / 256;

    // ---- layer 0 (no residual) ----
    k_gemm<<<gemmGrid, 256, GEMM_SMEM>>>(0, x, W0, n);
    k_gather<<<gatherGrid, 256>>>(b0, 0, nullptr, n);
    k_bnzero<<<1, D>>>();
    k_stats<<<1024, D>>>(n);
    k_bnfin<<<1, D>>>(gamma, beta, 1.0f / n);
    k_norm<<<normGrid, 256>>>(0, 1, total4);    // -> g_xa

    // ---- middle layers (residual) ----
    int xs = 1;
    for (int i = 0; i < 4; i++) {
        k_gemm<<<gemmGrid, 256, GEMM_SMEM>>>(xs, x, Wmid + (size_t)i * D * D, n);
        k_gather<<<gatherGrid, 256>>>(bmid + (size_t)i * D, 0, nullptr, n);
        k_bnzero<<<1, D>>>();
        k_stats<<<1024, D>>>(n);
        k_bnfin<<<1, D>>>(gamma + (size_t)(i + 1) * D, beta + (size_t)(i + 1) * D,
                          1.0f / n);
        k_norm<<<normGrid, 256>>>(xs, 3 - xs, total4);
        xs = 3 - xs;
    }

    // ---- output layer: GEMM + aggregation straight into d_out ----
    k_gemm<<<gemmGrid, 256, GEMM_SMEM>>>(xs, x, Wlast, n);
    k_gather<<<gatherGrid, 256>>>(blast, 1, (float*)d_out, n);
}

// round 8
// speedup vs baseline: 1.0811x; 1.0811x over previous
#include <cuda_runtime.h>
#include <cuda_bf16.h>
#include <math.h>

#define NN 100000
#define EE 1600000
#define D  128
#define BN_EPS 1e-5f

// ---------------- scratch (device globals; allocation-free kernel_launch) ----
__device__ float g_h [NN * D];
__device__ float g_y [NN * D];
__device__ float g_xa[NN * D];
__device__ float g_xb[NN * D];

__device__ int   g_deg[NN];
__device__ float g_dinv[NN];
__device__ int   g_incl[NN];
__device__ int   g_start[NN];
__device__ int   g_cursor[NN];
__device__ int   g_bsum[256];
__device__ int   g_boff[256];

__device__ int   g_csr_src[EE];
__device__ float g_csr_w [EE];

__device__ float g_sum[D], g_sq[D], g_scale[D], g_shift[D];

__device__ int   g_is64;

// ---------------- edge-index dtype detection --------------------------------
__global__ void k_detect(const int* __restrict__ ei) {
    if (threadIdx.x == 0 && blockIdx.x == 0) {
        int is64 = 1;
        #pragma unroll
        for (int i = 0; i < 16; i++)
            if (ei[2 * i + 1] != 0) is64 = 0;
        g_is64 = is64;
    }
}

__device__ __forceinline__ int load_idx(const void* ei, long long pos) {
    if (g_is64) return (int)((const long long*)ei)[pos];
    return ((const int*)ei)[pos];
}

// ---------------- pre-pass: degrees, dinv, CSR ------------------------------
__global__ void k_zero_deg(int n) {
    int i = blockIdx.x * blockDim.x + threadIdx.x;
    if (i < n) g_deg[i] = 0;
}

__global__ void k_deg(const void* __restrict__ ei, int e, int n) {
    int i = blockIdx.x * blockDim.x + threadIdx.x;
    if (i < e) {
        int dst = load_idx(ei, (long long)e + i);
        if ((unsigned)dst < (unsigned)n)
            atomicAdd(&g_deg[dst], 1);
    }
}

__global__ void k_dinv(int n) {
    int i = blockIdx.x * blockDim.x + threadIdx.x;
    if (i < n) g_dinv[i] = rsqrtf((float)(g_deg[i] + 1));   // +1 self loop
}

__global__ void k_scan_a(int n) {
    __shared__ int s[1024];
    int t = threadIdx.x;
    int i = blockIdx.x * 1024 + t;
    int v = (i < n) ? g_deg[i] : 0;
    s[t] = v;
    __syncthreads();
    for (int off = 1; off < 1024; off <<= 1) {
        int u = (t >= off) ? s[t - off] : 0;
        __syncthreads();
        s[t] += u;
        __syncthreads();
    }
    if (i < n) g_incl[i] = s[t];
    if (t == 1023) g_bsum[blockIdx.x] = s[1023];
}

__global__ void k_scan_b(int nb) {
    if (threadIdx.x == 0) {
        int acc = 0;
        for (int b = 0; b < nb; b++) { g_boff[b] = acc; acc += g_bsum[b]; }
    }
}

__global__ void k_scan_c(int n) {
    int i = blockIdx.x * blockDim.x + threadIdx.x;
    if (i < n) {
        int st = g_incl[i] + g_boff[i >> 10] - g_deg[i];
        g_start[i]  = st;
        g_cursor[i] = st;
    }
}

__global__ void k_fill(const void* __restrict__ ei, int e, int n) {
    int i = blockIdx.x * blockDim.x + threadIdx.x;
    if (i < e) {
        int s = load_idx(ei, i);
        int d = load_idx(ei, (long long)e + i);
        if ((unsigned)s < (unsigned)n && (unsigned)d < (unsigned)n) {
            int p = atomicAdd(&g_cursor[d], 1);
            if ((unsigned)p < (unsigned)EE) {
                g_csr_src[p] = s;
                g_csr_w[p]   = g_dinv[s] * g_dinv[d];
            }
        }
    }
}

// ============================================================================
// Tensor-core GEMM via mma.sync (bf16, fp32 accum) — base-target safe.
// h = x @ W, fp32 emulated with 3-term bf16 split: xh*wh + xl*wh + xh*wl.
// Per CTA: 128x128 M-tile; 8 warps, each 32(M) x 64(N).
// ============================================================================

#define MM_STRIDE 136                       // bf16 elems/row (+8 pad), 272 B
#define MM_ROWB   (MM_STRIDE * 2)
#define MM_TILE   (128 * MM_ROWB)           // 34816 B
#define MM_A_HI   0
#define MM_A_LO   MM_TILE
#define MM_B_HI   (2 * MM_TILE)
#define MM_B_LO   (3 * MM_TILE)
#define MM_SMEM   (4 * MM_TILE)             // 139264 B

__device__ __forceinline__ unsigned mm_s2u(const void* p) {
    unsigned a;
    asm("{ .reg .u64 t; cvta.to.shared.u64 t, %1; cvt.u32.u64 %0, t; }"
        : "=r"(a) : "l"(p));
    return a;
}

__device__ __forceinline__ void ldm_x4(unsigned r[4], unsigned addr) {
    asm volatile("ldmatrix.sync.aligned.m8n8.x4.shared.b16 {%0,%1,%2,%3}, [%4];"
                 : "=r"(r[0]), "=r"(r[1]), "=r"(r[2]), "=r"(r[3]) : "r"(addr));
}

__device__ __forceinline__ void mma16816(float c[4], const unsigned a[4],
                                         unsigned b0, unsigned b1) {
    asm volatile(
        "mma.sync.aligned.m16n8k16.row.col.f32.bf16.bf16.f32 "
        "{%0,%1,%2,%3}, {%4,%5,%6,%7}, {%8,%9}, {%0,%1,%2,%3};"
        : "+f"(c[0]), "+f"(c[1]), "+f"(c[2]), "+f"(c[3])
        : "r"(a[0]), "r"(a[1]), "r"(a[2]), "r"(a[3]), "r"(b0), "r"(b1));
}

__device__ __forceinline__ void mm_split(float v, unsigned short& h,
                                         unsigned short& l) {
    __nv_bfloat16 bh = __float2bfloat16(v);
    float rem = v - __bfloat162float(bh);
    __nv_bfloat16 bl = __float2bfloat16(rem);
    h = __bfloat16_as_ushort(bh);
    l = __bfloat16_as_ushort(bl);
}

__device__ __forceinline__ const float* sel_x(int s, const float* ext) {
    return (s == 0) ? ext : ((s == 1) ? g_xa : g_xb);
}

__global__ __launch_bounds__(256)
void k_gemm_mma(int xsel, const float* __restrict__ xext,
                const float* __restrict__ W, int n) {
    extern __shared__ char sm[];
    unsigned sb = mm_s2u(sm);
    int tid  = threadIdx.x;
    int wid  = tid >> 5;
    int lane = tid & 31;
    const float* x = sel_x(xsel, xext);
    int m0 = blockIdx.x * 128;

    // ---- stage A (x tile): thread = (row, col-half); split fp32 -> hi/lo ----
    {
        int r  = tid >> 1;
        int c0 = (tid & 1) * 64;
        int row = m0 + r;
        bool ok = (row < n);
        const float4* xr = (const float4*)(x + (size_t)(ok ? row : 0) * D + c0);
        char* ah = sm + MM_A_HI + r * MM_ROWB + c0 * 2;
        char* al = sm + MM_A_LO + r * MM_ROWB + c0 * 2;
        #pragma unroll
        for (int c = 0; c < 64; c += 4) {
            float4 v = make_float4(0.f, 0.f, 0.f, 0.f);
            if (ok) v = xr[c >> 2];
            unsigned short h0, h1, h2, h3, l0, l1, l2, l3;
            mm_split(v.x, h0, l0); mm_split(v.y, h1, l1);
            mm_split(v.z, h2, l2); mm_split(v.w, h3, l3);
            uint2 hp, lp;
            hp.x = (unsigned)h0 | ((unsigned)h1 << 16);
            hp.y = (unsigned)h2 | ((unsigned)h3 << 16);
            lp.x = (unsigned)l0 | ((unsigned)l1 << 16);
            lp.y = (unsigned)l2 | ((unsigned)l3 << 16);
            *(uint2*)(ah + c * 2) = hp;
            *(uint2*)(al + c * 2) = lp;
        }
    }

    // ---- stage B = W^T (row = out-channel, col = k) ----
    {
        int nn_ = tid >> 1;
        int k0  = (tid & 1) * 64;
        char* bh = sm + MM_B_HI + nn_ * MM_ROWB + k0 * 2;
        char* bl = sm + MM_B_LO + nn_ * MM_ROWB + k0 * 2;
        #pragma unroll 8
        for (int k = 0; k < 64; k += 2) {
            float w0 = W[(size_t)(k0 + k)     * D + nn_];
            float w1 = W[(size_t)(k0 + k + 1) * D + nn_];
            unsigned short h0, h1, l0, l1;
            mm_split(w0, h0, l0); mm_split(w1, h1, l1);
            *(unsigned*)(bh + k * 2) = (unsigned)h0 | ((unsigned)h1 << 16);
            *(unsigned*)(bl + k * 2) = (unsigned)l0 | ((unsigned)l1 << 16);
        }
    }
    __syncthreads();

    // ---- warp tile: 32 (M) x 64 (N) ----
    int wm = (wid & 3) * 32;
    int wn = (wid >> 2) * 64;

    float c[2][8][4];
    #pragma unroll
    for (int mi = 0; mi < 2; mi++)
        #pragma unroll
        for (int nb = 0; nb < 8; nb++)
            #pragma unroll
            for (int q = 0; q < 4; q++) c[mi][nb][q] = 0.f;

    // lane-dependent smem address pieces
    int aRow = lane & 15;                 // +((lane>>4)<<3) on the k axis
    int aKof = (lane >> 4) << 3;
    int bRow = (lane & 7) + ((lane >> 4) << 3);
    int bKof = (lane & 8);

    unsigned aBase0 = sb + MM_A_HI;       // per-term below
    #pragma unroll
    for (int term = 0; term < 3; term++) {
        unsigned aT = aBase0 + ((term == 1) ? (MM_A_LO - MM_A_HI) : 0);
        unsigned bT = sb + ((term == 2) ? MM_B_LO : MM_B_HI);
        unsigned aAdr0 = aT + (wm + aRow) * MM_ROWB + aKof * 2;
        unsigned aAdr1 = aAdr0 + 16 * MM_ROWB;
        unsigned bAdr  = bT + (wn + bRow) * MM_ROWB + bKof * 2;

        #pragma unroll
        for (int k = 0; k < 8; k++) {
            unsigned a0[4], a1[4];
            ldm_x4(a0, aAdr0 + k * 32);
            ldm_x4(a1, aAdr1 + k * 32);
            #pragma unroll
            for (int nb = 0; nb < 4; nb++) {
                unsigned b[4];
                ldm_x4(b, bAdr + nb * 16 * MM_ROWB + k * 32);
                mma16816(c[0][2 * nb],     a0, b[0], b[1]);
                mma16816(c[0][2 * nb + 1], a0, b[2], b[3]);
                mma16816(c[1][2 * nb],     a1, b[0], b[1]);
                mma16816(c[1][2 * nb + 1], a1, b[2], b[3]);
            }
        }
    }

    // ---- epilogue: write fragments to g_h ----
    #pragma unroll
    for (int mi = 0; mi < 2; mi++) {
        int rowA = m0 + wm + mi * 16 + (lane >> 2);
        int rowB = rowA + 8;
        #pragma unroll
        for (int nb = 0; nb < 8; nb++) {
            int col = wn + nb * 8 + (lane & 3) * 2;
            if (rowA < n) {
                float2 v = make_float2(c[mi][nb][0], c[mi][nb][1]);
                *(float2*)(g_h + (size_t)rowA * D + col) = v;
            }
            if (rowB < n) {
                float2 v = make_float2(c[mi][nb][2], c[mi][nb][3]);
                *(float2*)(g_h + (size_t)rowB * D + col) = v;
            }
        }
    }
}

// ---------------- aggregation: y[i] = b + dinv[i]^2*h[i] + sum w*h[src] -----
__global__ void k_gather(const float* __restrict__ bias, int ysel,
                         float* __restrict__ yext, int n) {
    int gw   = (blockIdx.x * blockDim.x + threadIdx.x) >> 5;
    int lane = threadIdx.x & 31;
    if (gw >= n) return;
    int i = gw;
    float* y = (ysel == 0) ? g_y : yext;

    float dv = g_dinv[i];
    float4 acc = ((const float4*)bias)[lane];
    float4 hv  = ((const float4*)(g_h + (size_t)i * D))[lane];
    float c = dv * dv;
    acc.x += c * hv.x; acc.y += c * hv.y; acc.z += c * hv.z; acc.w += c * hv.w;

    int j = g_start[i];
    int e = j + g_deg[i];
    if (e > EE) e = EE;
    if (j < e) {
        int   src = g_csr_src[j];
        float w   = g_csr_w[j];
        while (j < e) {
            int nj = j + 1;
            int nsrc = 0; float nw = 0.f;
            if (nj < e) { nsrc = g_csr_src[nj]; nw = g_csr_w[nj]; }
            float4 hs = ((const float4*)(g_h + (size_t)src * D))[lane];
            acc.x += w * hs.x; acc.y += w * hs.y;
            acc.z += w * hs.z; acc.w += w * hs.w;
            src = nsrc; w = nw; j = nj;
        }
    }
    ((float4*)(y + (size_t)i * D))[lane] = acc;
}

// ---------------- BatchNorm ---------------------------------------------------
__global__ void k_bnzero() {
    int c = threadIdx.x;
    g_sum[c] = 0.f; g_sq[c] = 0.f;
}

__global__ void k_stats(int n) {
    int c = threadIdx.x;
    float s = 0.f, q = 0.f;
    for (int r = blockIdx.x; r < n; r += gridDim.x) {
        float v = g_y[(size_t)r * D + c];
        s += v; q += v * v;
    }
    atomicAdd(&g_sum[c], s);
    atomicAdd(&g_sq[c],  q);
}

__global__ void k_bnfin(const float* __restrict__ gamma,
                        const float* __restrict__ beta, float inv_n) {
    int c = threadIdx.x;
    float mu  = g_sum[c] * inv_n;
    float var = g_sq[c] * inv_n - mu * mu;
    float sc  = gamma[c] * rsqrtf(var + BN_EPS);
    g_scale[c] = sc;
    g_shift[c] = beta[c] - mu * sc;
}

__global__ void k_norm(int resSel, int outSel, int total4) {
    int i = blockIdx.x * blockDim.x + threadIdx.x;
    if (i >= total4) return;
    int c4 = i & (D / 4 - 1);
    float4 v  = ((const float4*)g_y)[i];
    float4 sc = ((const float4*)g_scale)[c4];
    float4 sh = ((const float4*)g_shift)[c4];
    v.x = fmaxf(v.x * sc.x + sh.x, 0.f);
    v.y = fmaxf(v.y * sc.y + sh.y, 0.f);
    v.z = fmaxf(v.z * sc.z + sh.z, 0.f);
    v.w = fmaxf(v.w * sc.w + sh.w, 0.f);
    if (resSel) {
        const float4* res = (resSel == 1) ? (const float4*)g_xa : (const float4*)g_xb;
        float4 rv = res[i];
        v.x += rv.x; v.y += rv.y; v.z += rv.z; v.w += rv.w;
    }
    float4* out = (outSel == 1) ? (float4*)g_xa : (float4*)g_xb;
    out[i] = v;
}

// ---------------- launch ------------------------------------------------------
extern "C" void kernel_launch(void* const* d_in, const int* in_sizes, int n_in,
                              void* d_out, int out_size) {
    const float* x     = (const float*)d_in[0];
    const void*  ei    = d_in[1];
    const float* W0    = (const float*)d_in[2];
    const float* b0    = (const float*)d_in[3];
    const float* Wmid  = (const float*)d_in[4];
    const float* bmid  = (const float*)d_in[5];
    const float* Wlast = (const float*)d_in[6];
    const float* blast = (const float*)d_in[7];
    const float* gamma = (const float*)d_in[8];
    const float* beta  = (const float*)d_in[9];

    int n = in_sizes[0] / D;
    int e = in_sizes[1] / 2;

    cudaFuncSetAttribute(k_gemm_mma, cudaFuncAttributeMaxDynamicSharedMemorySize,
                         MM_SMEM);

    // ---- pre: dtype detect, degrees / dinv / CSR-by-dst ----
    k_detect<<<1, 32>>>((const int*)ei);
    k_zero_deg<<<(n + 255) / 256, 256>>>(n);
    k_deg<<<(e + 255) / 256, 256>>>(ei, e, n);
    k_dinv<<<(n + 255) / 256, 256>>>(n);
    int nb = (n + 1023) / 1024;
    k_scan_a<<<nb, 1024>>>(n);
    k_scan_b<<<1, 32>>>(nb);
    k_scan_c<<<(n + 255) / 256, 256>>>(n);
    k_fill<<<(e + 255) / 256, 256>>>(ei, e, n);

    int nTiles     = (n + 127) / 128;
    int gatherGrid = (n * 32 + 255) / 256;
    int total4     = n * (D / 4);
    int normGrid   = (total4 + 255) / 256;

    // ---- layer 0 (no residual) ----
    k_gemm_mma<<<nTiles, 256, MM_SMEM>>>(0, x, W0, n);
    k_gather<<<gatherGrid, 256>>>(b0, 0, nullptr, n);
    k_bnzero<<<1, D>>>();
    k_stats<<<1024, D>>>(n);
    k_bnfin<<<1, D>>>(gamma, beta, 1.0f / n);
    k_norm<<<normGrid, 256>>>(0, 1, total4);    // -> g_xa

    // ---- middle layers (residual) ----
    int xs = 1;
    for (int i = 0; i < 4; i++) {
        k_gemm_mma<<<nTiles, 256, MM_SMEM>>>(xs, x, Wmid + (size_t)i * D * D, n);
        k_gather<<<gatherGrid, 256>>>(bmid + (size_t)i * D, 0, nullptr, n);
        k_bnzero<<<1, D>>>();
        k_stats<<<1024, D>>>(n);
        k_bnfin<<<1, D>>>(gamma + (size_t)(i + 1) * D, beta + (size_t)(i + 1) * D,
                          1.0f / n);
        k_norm<<<normGrid, 256>>>(xs, 3 - xs, total4);
        xs = 3 - xs;
    }

    // ---- output layer: GEMM + aggregation straight into d_out ----
    k_gemm_mma<<<nTiles, 256, MM_SMEM>>>(xs, x, Wlast, n);
    k_gather<<<gatherGrid, 256>>>(blast, 1, (float*)d_out, n);
}